// round 13
// baseline (speedup 1.0000x reference)
#include <cuda_runtime.h>

#define Bn 4
#define Hq 512
#define Wq 512
#define Cn 128
#define Hon 502
#define Won 502
#define OFFS 2
#define TH 4
#define TW 64
#define NTX 32
#define NSL 12
#define NTHR 384
#define CCK 16
#define NCHUNK 8
#define QR 12
#define QW 72
#define QPAD 76
#define PPAD 68
#define QS_FLOATS (QR*CCK*QPAD)
#define PS_FLOATS (TH*CCK*PPAD)
#define TILE_FLOATS (QS_FLOATS + PS_FLOATS)
#define SMEM_BYTES (2 * TILE_FLOATS * 4)

#define FMA2(d, a, b) asm("fma.rn.f32x2 %0, %1, %2, %0;" : "+l"(d) : "l"(a), "l"(b))
#define PACK2(r, lo, hi) asm("mov.b64 %0, {%1, %2};" : "=l"(r) : "f"(lo), "f"(hi))
#define UNPACK2(lo, hi, r) asm("mov.b64 {%0, %1}, %2;" : "=f"(lo), "=f"(hi) : "l"(r))

__global__ __launch_bounds__(NTHR, 1)
void corr9x9_diag_kernel(const float* __restrict__ pg,
                         const float* __restrict__ qg,
                         float* __restrict__ outg)
{
    extern __shared__ __align__(16) float smem[];

    const int tx  = threadIdx.x;            // 0..31 (warp = one slot)
    const int r   = threadIdx.y;            // 0..11 diagonal (= h+dy)
    const int tid = tx + NTX * r;

    const int wo0 = blockIdx.x * TW;
    const int ho0 = blockIdx.y * TH;
    const int b   = blockIdx.z;

    const float* pb = pg + (size_t)b * Hon * Won * Cn;
    const float* qb = qg + (size_t)b * Hq  * Wq  * Cn;

    // combo table: h[i] = clamped max(0,r-8)+i; dy = r-h; valid if hh<=3 && hh<=r
    int hlo = r - 8; if (hlo < 0) hlo = 0;
    int hcl[4]; bool val[4];
    #pragma unroll
    for (int i = 0; i < 4; ++i) {
        int hh = hlo + i;
        val[i] = (hh <= 3) && (hh <= r);
        hcl[i] = (hh > 3) ? 3 : hh;
    }

    // staging offsets: q 9 iters, p 3 iters (mask); CCK=16, c4=flat&3 (64B granules)
    int qoff[9], qdst[9];
    #pragma unroll
    for (int i = 0; i < 9; ++i) {
        int flat = tid + i * NTHR;          // covers QR*QW*4 = 3456 exactly
        int c4 = flat & 3, t = flat >> 2;
        int w = t % QW, rr = t / QW;
        int hr = ho0 + OFFS + rr; if (hr > Hq - 1) hr = Hq - 1;
        int wr = wo0 + OFFS + w;  if (wr > Wq - 1) wr = Wq - 1;
        qoff[i] = (hr * Wq + wr) * Cn + c4 * 4;
        qdst[i] = (rr * CCK + 2 * c4) * QPAD + w;
    }
    int poff[3], pdst[3]; bool pok[3];
    #pragma unroll
    for (int i = 0; i < 3; ++i) {
        int flat = tid + i * NTHR;
        pok[i] = (flat < TH * TW * 4);      // 1024
        int f = pok[i] ? flat : 0;
        int c4 = f & 3, t = f >> 2;
        int w = t & (TW - 1), rw = t >> 6;
        int hr = ho0 + rw; if (hr > Hon - 1) hr = Hon - 1;
        int wr = wo0 + w;  if (wr > Won - 1) wr = Won - 1;
        poff[i] = (hr * Won + wr) * Cn + c4 * 4;
        pdst[i] = (rw * CCK + 2 * c4) * PPAD + w;
    }

    unsigned long long acc[4][9];
    #pragma unroll
    for (int i = 0; i < 4; ++i)
        #pragma unroll
        for (int d = 0; d < 9; ++d) acc[i][d] = 0ull;

    float4 hq[6], sq[3], sp[3];
    // STS helper macros (rho map: .x->+0, .y->+QPAD, .z->+8*QPAD, .w->+9*QPAD)
#define STQ(dst, i, v) { dst[qdst[i]] = v.x; dst[qdst[i]+QPAD] = v.y; \
                         dst[qdst[i]+8*QPAD] = v.z; dst[qdst[i]+9*QPAD] = v.w; }
#define STP(dst, i, v) if (pok[i]) { dst[pdst[i]] = v.x; dst[pdst[i]+PPAD] = v.y; \
                         dst[pdst[i]+8*PPAD] = v.z; dst[pdst[i]+9*PPAD] = v.w; }

    // prolog: chunk0 -> buf0; LDG held chunk1
    {
        #pragma unroll
        for (int i = 0; i < 6; ++i) hq[i] = *(const float4*)(qb + qoff[i]);
        #pragma unroll
        for (int i = 0; i < 3; ++i) sq[i] = *(const float4*)(qb + qoff[6 + i]);
        #pragma unroll
        for (int i = 0; i < 3; ++i) if (pok[i]) sp[i] = *(const float4*)(pb + poff[i]);
        float* q_s = smem; float* p_s = smem + QS_FLOATS;
        #pragma unroll
        for (int i = 0; i < 6; ++i) STQ(q_s, i, hq[i]);
        #pragma unroll
        for (int i = 0; i < 3; ++i) STQ(q_s, 6 + i, sq[i]);
        #pragma unroll
        for (int i = 0; i < 3; ++i) STP(p_s, i, sp[i]);
        #pragma unroll
        for (int i = 0; i < 6; ++i) hq[i] = *(const float4*)(qb + qoff[i] + CCK);
    }
    __syncthreads();

    const int px = 2 * tx;

    for (int k = 0; k < NCHUNK; ++k) {
        const float* q_s = smem + (k & 1) * TILE_FLOATS;
        const float* p_s = q_s + QS_FLOATS;

        #pragma unroll
        for (int c = 0; c < CCK; ++c) {
            const float* qw = q_s + (r * CCK + c) * QPAD + px;
            float qf[10];
            #pragma unroll
            for (int j = 0; j < 5; ++j) {
                float2 v = *(const float2*)(qw + 2 * j);
                qf[2 * j] = v.x; qf[2 * j + 1] = v.y;
            }
            unsigned long long pr[9];
            #pragma unroll
            for (int d = 0; d < 9; ++d) PACK2(pr[d], qf[d], qf[d + 1]);
            #pragma unroll
            for (int i = 0; i < 4; ++i) {
                float2 pv = *(const float2*)(p_s + (hcl[i] * CCK + c) * PPAD + px);
                unsigned long long pp;
                PACK2(pp, pv.x, pv.y);
                #pragma unroll
                for (int d = 0; d < 9; ++d) FMA2(acc[i][d], pp, pr[d]);
            }
        }

        if (k + 1 < NCHUNK) {
            float* q_d = smem + ((k + 1) & 1) * TILE_FLOATS;
            float* p_d = q_d + QS_FLOATS;
            int cc1 = (k + 1) * CCK;
            // issue streamed LDGs first (hidden by held STS)
            #pragma unroll
            for (int i = 0; i < 3; ++i) sq[i] = *(const float4*)(qb + qoff[6 + i] + cc1);
            #pragma unroll
            for (int i = 0; i < 3; ++i) if (pok[i]) sp[i] = *(const float4*)(pb + poff[i] + cc1);
            #pragma unroll
            for (int i = 0; i < 6; ++i) STQ(q_d, i, hq[i]);
            #pragma unroll
            for (int i = 0; i < 3; ++i) STQ(q_d, 6 + i, sq[i]);
            #pragma unroll
            for (int i = 0; i < 3; ++i) STP(p_d, i, sp[i]);
            if (k + 2 < NCHUNK) {
                int cc2 = (k + 2) * CCK;
                #pragma unroll
                for (int i = 0; i < 6; ++i) hq[i] = *(const float4*)(qb + qoff[i] + cc2);
            }
            __syncthreads();
        }
    }

    // epilogue: smem-staged coalesced output, 2 slabs of 2 rows
    float* out_s = smem;   // [2][TW][81] = 10368 floats
    #pragma unroll
    for (int s = 0; s < 2; ++s) {
        __syncthreads();
        #pragma unroll
        for (int i = 0; i < 4; ++i) {
            if (val[i] && ((hcl[i] >> 1) == s)) {
                int dy = r - hcl[i];
                float* d0 = out_s + (((hcl[i] & 1) * TW) + px) * 81 + dy * 9;
                #pragma unroll
                for (int d = 0; d < 9; ++d) {
                    float lo, hi;
                    UNPACK2(lo, hi, acc[i][d]);
                    d0[d] = lo; d0[81 + d] = hi;
                }
            }
        }
        __syncthreads();
        #pragma unroll
        for (int kk = 0; kk < 27; ++kk) {
            int f = tid + kk * NTHR;
            int rr = f / (TW * 81);
            int rem = f - rr * (TW * 81);
            int pxx = rem / 81;
            int ho = ho0 + 2 * s + rr;
            if (ho < Hon && (wo0 + pxx) < Won) {
                size_t dst = ((size_t)(b * Hon + ho) * Won + wo0) * 81 + rem;
                __stcs(&outg[dst], out_s[f]);
            }
        }
    }
}

extern "C" void kernel_launch(void* const* d_in, const int* in_sizes, int n_in,
                              void* d_out, int out_size)
{
    const float* p = (const float*)d_in[0];
    const float* q = (const float*)d_in[1];
    float* out = (float*)d_out;

    cudaFuncSetAttribute(corr9x9_diag_kernel,
                         cudaFuncAttributeMaxDynamicSharedMemorySize, SMEM_BYTES);

    dim3 block(NTX, NSL);                      // 32 x 12 = 384
    dim3 grid((Won + TW - 1) / TW,             // 8
              (Hon + TH - 1) / TH,             // 126
              Bn);                             // 4
    corr9x9_diag_kernel<<<grid, block, SMEM_BYTES>>>(p, q, out);
}